// round 16
// baseline (speedup 1.0000x reference)
#include <cuda_runtime.h>
#include <cuda_fp16.h>

// ---------------- problem constants ----------------
#define T_SEQ 2048
#define ISZ   1024
#define HSZ   2048
#define OSZ   512
#define NCTA  148
#define RS    13                 // rows per CTA
#define BASE_ROWS (NCTA*RS)      // 1924
#define EXTRA_ROWS (HSZ - BASE_ROWS) // 124 extra rows (one per CTA < 124)

// SMEM layout (bytes): ws 12 row-gates * 2048 * 2 = 49152 | hsh 2*4096 | a_s 256 | c_s 64
#define WS_BYTES   49152
#define HSH_OFF    WS_BYTES
#define AS_OFF     (HSH_OFF + 2 * 4096)
#define CS_OFF     (AS_OFF + 256)
#define SMEM_BYTES (CS_OFF + 64)

// ---------------- device globals (scratch; no allocation allowed) ----------------
__device__ __half   g_Wh[(size_t)4 * HSZ * HSZ];        // fp16 recurrent weights [g][j][k]
__device__ float    g_Gx[(size_t)T_SEQ * 4 * HSZ];      // [t][g*H + j] = Wx_g @ x_t + b_g
__device__ __align__(16) unsigned g_htag[2][HSZ];       // {tag:16 | h_fp16:16}, dbl-buffered by parity

// ---------------- weight conversion: fp32 -> fp16 (recurrent halves only) ----------------
__global__ void conv_w_kernel(const float* __restrict__ Wf, const float* __restrict__ Wi,
                              const float* __restrict__ Wc, const float* __restrict__ Wo) {
    const float* Ws[4] = {Wf, Wi, Wc, Wo};
    size_t idx = (size_t)blockIdx.x * 256 + threadIdx.x;   // one float4 per thread
    int g   = (int)(idx >> 20);                            // 2048 rows * 512 float4/row
    int rem = (int)(idx & 0xFFFFF);
    int j   = rem >> 9;
    int kv  = rem & 511;
    float4 v = *(const float4*)(Ws[g] + (size_t)j * 3072 + (size_t)kv * 4);
    __half2 h0 = __floats2half2_rn(v.x, v.y);
    __half2 h1 = __floats2half2_rn(v.z, v.w);
    __half2* dst = (__half2*)(g_Wh + ((size_t)(g * HSZ + j)) * HSZ + (size_t)kv * 4);
    dst[0] = h0; dst[1] = h1;
}

// ---------------- NT GEMM descriptors: C[M,N] = A[M,K] * B[N,K]^T + bias(n) ----------------
// B rows indirected: row n lives at base[n>>11] + (n&2047)*ldb + koff.
struct BDesc {
    const float* base[4];
    const float* bias[4];
    int ldb;
    int koff;
};

// 128x128 tile, 8x8 per thread, BK=8, reg-prefetch double buffer. For the big Gx GEMM.
__global__ __launch_bounds__(256) void nt_sgemm128(
    const float* __restrict__ A, int lda,
    BDesc bd,
    float* __restrict__ C, int ldc,
    int K)
{
    __shared__ float As[8][128];
    __shared__ float Bs[8][128];
    int tid = threadIdx.x;
    int m0 = blockIdx.y * 128, n0 = blockIdx.x * 128;
    int lr = tid >> 1;            // 0..127
    int lc = (tid & 1) * 4;       // 0 or 4
    const float* arow = A + (size_t)(m0 + lr) * lda + lc;
    int nb = n0 + lr;
    const float* brow = bd.base[nb >> 11] + (size_t)(nb & 2047) * bd.ldb + bd.koff + lc;
    int tx = (tid & 15) * 8;
    int ty = (tid >> 4) * 8;
    float acc[8][8] = {};

    float4 av = *(const float4*)(arow);
    float4 bv = *(const float4*)(brow);
    for (int k0 = 0; k0 < K; k0 += 8) {
        __syncthreads();
        As[lc + 0][lr] = av.x; As[lc + 1][lr] = av.y;
        As[lc + 2][lr] = av.z; As[lc + 3][lr] = av.w;
        Bs[lc + 0][lr] = bv.x; Bs[lc + 1][lr] = bv.y;
        Bs[lc + 2][lr] = bv.z; Bs[lc + 3][lr] = bv.w;
        __syncthreads();
        if (k0 + 8 < K) {                 // prefetch next slab; overlaps compute below
            av = *(const float4*)(arow + k0 + 8);
            bv = *(const float4*)(brow + k0 + 8);
        }
#pragma unroll
        for (int k = 0; k < 8; k++) {
            float a[8], b[8];
            *(float4*)(a + 0) = *(const float4*)&As[k][ty];
            *(float4*)(a + 4) = *(const float4*)&As[k][ty + 4];
            *(float4*)(b + 0) = *(const float4*)&Bs[k][tx];
            *(float4*)(b + 4) = *(const float4*)&Bs[k][tx + 4];
#pragma unroll
            for (int mi = 0; mi < 8; mi++)
#pragma unroll
                for (int ni = 0; ni < 8; ni++)
                    acc[mi][ni] += a[mi] * b[ni];
        }
    }

    float bias[8];
#pragma unroll
    for (int u = 0; u < 8; u++) {
        int n = n0 + tx + u;
        bias[u] = bd.bias[n >> 11][n & 2047];
    }
#pragma unroll
    for (int mi = 0; mi < 8; mi++) {
        float4 o0, o1;
        o0.x = acc[mi][0] + bias[0]; o0.y = acc[mi][1] + bias[1];
        o0.z = acc[mi][2] + bias[2]; o0.w = acc[mi][3] + bias[3];
        o1.x = acc[mi][4] + bias[4]; o1.y = acc[mi][5] + bias[5];
        o1.z = acc[mi][6] + bias[6]; o1.w = acc[mi][7] + bias[7];
        float* cp = C + (size_t)(m0 + ty + mi) * ldc + n0 + tx;
        *(float4*)cp = o0;
        *(float4*)(cp + 4) = o1;
    }
}

// 64x64 tile, 4x4 per thread. For the small y-GEMM (better grid coverage).
__global__ __launch_bounds__(256) void nt_sgemm(
    const float* __restrict__ A, int lda,
    BDesc bd,
    float* __restrict__ C, int ldc,
    int K)
{
    __shared__ float As[16][64];
    __shared__ float Bs[16][64];
    int tid = threadIdx.x;
    int m0 = blockIdx.y * 64, n0 = blockIdx.x * 64;
    int lrow = tid >> 2;
    int lkv  = (tid & 3) * 4;
    const float* arow = A + (size_t)(m0 + lrow) * lda + lkv;
    int nb = n0 + lrow;
    const float* brow = bd.base[nb >> 11] + (size_t)(nb & 2047) * bd.ldb + bd.koff + lkv;
    int tx = (tid & 15) * 4;
    int ty = (tid >> 4) * 4;
    float acc[4][4] = {};

    for (int k0 = 0; k0 < K; k0 += 16) {
        float4 av = *(const float4*)(arow + k0);
        float4 bv = *(const float4*)(brow + k0);
        __syncthreads();
        As[lkv + 0][lrow] = av.x; As[lkv + 1][lrow] = av.y;
        As[lkv + 2][lrow] = av.z; As[lkv + 3][lrow] = av.w;
        Bs[lkv + 0][lrow] = bv.x; Bs[lkv + 1][lrow] = bv.y;
        Bs[lkv + 2][lrow] = bv.z; Bs[lkv + 3][lrow] = bv.w;
        __syncthreads();
#pragma unroll
        for (int k = 0; k < 16; k++) {
            float4 a4 = *(const float4*)&As[k][ty];
            float4 b4 = *(const float4*)&Bs[k][tx];
            acc[0][0] += a4.x * b4.x; acc[0][1] += a4.x * b4.y; acc[0][2] += a4.x * b4.z; acc[0][3] += a4.x * b4.w;
            acc[1][0] += a4.y * b4.x; acc[1][1] += a4.y * b4.y; acc[1][2] += a4.y * b4.z; acc[1][3] += a4.y * b4.w;
            acc[2][0] += a4.z * b4.x; acc[2][1] += a4.z * b4.y; acc[2][2] += a4.z * b4.z; acc[2][3] += a4.z * b4.w;
            acc[3][0] += a4.w * b4.x; acc[3][1] += a4.w * b4.y; acc[3][2] += a4.w * b4.z; acc[3][3] += a4.w * b4.w;
        }
    }

    float bias[4];
#pragma unroll
    for (int u = 0; u < 4; u++) {
        int n = n0 + tx + u;
        bias[u] = bd.bias[n >> 11][n & 2047];
    }
#pragma unroll
    for (int mi = 0; mi < 4; mi++) {
        float4 o;
        o.x = acc[mi][0] + bias[0];
        o.y = acc[mi][1] + bias[1];
        o.z = acc[mi][2] + bias[2];
        o.w = acc[mi][3] + bias[3];
        *(float4*)(C + (size_t)(m0 + ty + mi) * ldc + n0 + tx) = o;
    }
}

// ---------------- persistent recurrent kernel ----------------
__device__ __forceinline__ float fast_sig(float x)  { return 1.f / (1.f + __expf(-x)); }
__device__ __forceinline__ float fast_tanh(float x) { return 2.f / (1.f + __expf(-2.f * x)) - 1.f; }

__device__ __forceinline__ uint2 ld_rlx2(const unsigned* p) {
    uint2 v;
    asm volatile("ld.relaxed.gpu.global.v2.u32 {%0,%1}, [%2];"
                 : "=r"(v.x), "=r"(v.y) : "l"(p) : "memory");
    return v;
}
__device__ __forceinline__ void st_rlx(unsigned* p, unsigned v) {
    asm volatile("st.relaxed.gpu.global.u32 [%0], %1;" :: "l"(p), "r"(v) : "memory");
}

// 16-term fp16 chain: 8 HFMA2 across two uint4 weight vectors, one fp32 promote.
#define MAC16(VA, VB, ACC) do {                                      \
    __half2 _p = __hmul2(*(__half2*)&(VA).x, a0);                    \
    _p = __hfma2(*(__half2*)&(VA).y, a1, _p);                        \
    _p = __hfma2(*(__half2*)&(VA).z, a2, _p);                        \
    _p = __hfma2(*(__half2*)&(VA).w, a3, _p);                        \
    _p = __hfma2(*(__half2*)&(VB).x, b0, _p);                        \
    _p = __hfma2(*(__half2*)&(VB).y, b1, _p);                        \
    _p = __hfma2(*(__half2*)&(VB).z, b2, _p);                        \
    _p = __hfma2(*(__half2*)&(VB).w, b3, _p);                        \
    float2 _pf = __half22float2(_p);                                 \
    (ACC) += _pf.x + _pf.y;                                          \
} while (0)

__global__ __launch_bounds__(256, 1) void lstm_kernel(float* __restrict__ hid) {
    extern __shared__ unsigned char smem[];
    __half* ws  = (__half*)smem;                // 12 row-gates (rg 40..51) * 2048 halfs
    float*  a_s = (float*)(smem + AS_OFF);      // 56 pre-activations
    float*  c_s = (float*)(smem + CS_OFF);      // 14 cell states

    int cta  = blockIdx.x;
    int tid  = threadIdx.x;
    int w    = tid >> 5;
    int lane = tid & 31;
    bool has_extra = (cta < EXTRA_ROWS);
    int R    = RS + (has_extra ? 1 : 0);
    int row0 = cta * RS;

    // ---- register-resident weights: q = 0..4 (row-gates rg = 8q+w), 160 regs/thread ----
    uint4 wreg[5][8];
    {
        const uint4* base = (const uint4*)g_Wh;
#pragma unroll
        for (int q = 0; q < 5; q++) {
            int rg = 8 * q + w;
            int g = rg & 3, r = rg >> 2;
            const uint4* src = base + ((size_t)(g * HSZ + row0 + r)) * 256 + lane;
#pragma unroll
            for (int i = 0; i < 8; i++) wreg[q][i] = __ldg(src + 32 * i);
        }
    }
    // ---- register-resident extra row (warps 4..7 of CTAs 0..123): 32 regs ----
    uint4 wx[8];
#pragma unroll
    for (int i = 0; i < 8; i++) wx[i] = make_uint4(0, 0, 0, 0);
    if (has_extra && w >= 4) {
        const uint4* src = (const uint4*)g_Wh
                         + ((size_t)((w - 4) * HSZ + BASE_ROWS + cta)) * 256 + lane;
#pragma unroll
        for (int i = 0; i < 8; i++) wx[i] = __ldg(src + 32 * i);
    }

    // ---- SMEM weights: row-gates rg = 40..51 (q=5 all warps; q=6 for w<4) ----
    {
        const uint4* src = (const uint4*)g_Wh;
        uint4* dst = (uint4*)ws;
        for (int ci = tid; ci < 12 * 256; ci += 256) {
            int idx = ci >> 8, off = ci & 255;
            int rg = 40 + idx;
            int g = rg & 3, r = rg >> 2;
            dst[ci] = src[((size_t)(g * HSZ + row0 + r)) * 256 + off];
        }
    }
    if (tid < 16) c_s[tid] = 0.f;
    __syncthreads();

    const uint4* ws5 = (const uint4*)ws + (size_t)w * 256 + lane;        // rg = 40+w
    const uint4* ws6 = (const uint4*)ws + (size_t)(8 + w) * 256 + lane;  // rg = 48+w (w<4)

    for (int t = 0; t < T_SEQ; t++) {
        // h staging buffer for this step (parity); next step uses the other one,
        // so straggler warps may still be reading the old buffer — no loop-end sync needed
        __half* hsh = (__half*)(smem + HSH_OFF + (t & 1) * 4096);

        // ---- prefetch Gx + cell state (independent of h_{t-1}; overlaps the wait) ----
        float gxv0 = 0.f, gxv1 = 0.f, gxv2 = 0.f, gxv3 = 0.f, cold = 0.f;
        int jmine = 0;
        if (tid < R) {
            jmine = (tid < RS) ? (row0 + tid) : (BASE_ROWS + cta);
            const float* gp = g_Gx + (size_t)t * (4 * HSZ) + jmine;
            gxv0 = __ldg(gp);
            gxv1 = __ldg(gp + HSZ);
            gxv2 = __ldg(gp + 2 * HSZ);
            gxv3 = __ldg(gp + 3 * HSZ);
            cold = c_s[tid];
        }

        // ---- acquire h_{t-1}: tagged-word poll; long spin window before any sleep ----
        if (t == 0) {
            ((uint4*)hsh)[tid] = make_uint4(0, 0, 0, 0);   // 256*16B = 4KB
        } else {
            const unsigned* src = g_htag[(t - 1) & 1];
            unsigned res[4];
            unsigned pend = 0xFu;
            unsigned tg = (unsigned)t;
            int spins = 0;
            for (;;) {
#pragma unroll
                for (int i = 0; i < 4; i++) {
                    if (pend & (1u << i)) {
                        uint2 v = ld_rlx2(src + 2 * tid + 512 * i);
                        if ((v.x >> 16) == tg && (v.y >> 16) == tg) {
                            res[i] = (v.x & 0xFFFFu) | (v.y << 16);
                            pend &= ~(1u << i);
                        }
                    }
                }
                if (!pend) break;
                if (++spins > 24) __nanosleep(32);   // expected wait is short: spin freely first
            }
            unsigned* hw = (unsigned*)hsh;
#pragma unroll
            for (int i = 0; i < 4; i++) hw[tid + 256 * i] = res[i];
        }
        __syncthreads();

        // ---- 56 dot products, 16-term fp16 chains (promote once per 2 iters) ----
        float acc[7] = {0.f, 0.f, 0.f, 0.f, 0.f, 0.f, 0.f};
        const uint4* h16 = (const uint4*)hsh;
#pragma unroll
        for (int i2 = 0; i2 < 4; i2++) {
            int ia = 2 * i2, ib = 2 * i2 + 1;
            uint4 hva = h16[lane + 32 * ia];
            uint4 hvb = h16[lane + 32 * ib];
            __half2 a0 = *(__half2*)&hva.x, a1 = *(__half2*)&hva.y;
            __half2 a2 = *(__half2*)&hva.z, a3 = *(__half2*)&hva.w;
            __half2 b0 = *(__half2*)&hvb.x, b1 = *(__half2*)&hvb.y;
            __half2 b2 = *(__half2*)&hvb.z, b3 = *(__half2*)&hvb.w;
            MAC16(wreg[0][ia], wreg[0][ib], acc[0]);
            MAC16(wreg[1][ia], wreg[1][ib], acc[1]);
            MAC16(wreg[2][ia], wreg[2][ib], acc[2]);
            MAC16(wreg[3][ia], wreg[3][ib], acc[3]);
            MAC16(wreg[4][ia], wreg[4][ib], acc[4]);
            {   // q = 5 from SMEM
                uint4 va = ws5[32 * ia];
                uint4 vb = ws5[32 * ib];
                MAC16(va, vb, acc[5]);
            }
            if (w < 4) {                           // rg = 48+w from SMEM
                uint4 va = ws6[32 * ia];
                uint4 vb = ws6[32 * ib];
                MAC16(va, vb, acc[6]);
            } else if (has_extra) {                // extra row from registers
                MAC16(wx[ia], wx[ib], acc[6]);
            }
        }

        // ---- joint butterfly reduction of all 7 accumulators (interleaved chains) ----
#pragma unroll
        for (int off = 16; off; off >>= 1) {
#pragma unroll
            for (int q = 0; q < 7; q++)
                acc[q] += __shfl_xor_sync(0xffffffffu, acc[q], off);
        }
        if (lane == 0) {
#pragma unroll
            for (int q = 0; q < 6; q++) a_s[8 * q + w] = acc[q];
            if (w < 4 || has_extra) a_s[48 + w] = acc[6];
        }
        __syncthreads();

        // ---- gate math + state update + publish (one thread per row) ----
        if (tid < R) {
            float af, ai, ac, ao;
            if (tid < RS) {
                af = a_s[tid * 4 + 0]; ai = a_s[tid * 4 + 1];
                ac = a_s[tid * 4 + 2]; ao = a_s[tid * 4 + 3];
            } else {
                af = a_s[52]; ai = a_s[53]; ac = a_s[54]; ao = a_s[55];
            }
            af += gxv0; ai += gxv1; ac += gxv2; ao += gxv3;
            float f  = fast_sig(af);
            float ii = fast_sig(ai);
            float cc = fast_tanh(ac);
            float o  = fast_sig(ao);
            float c  = f * cold + ii * cc;
            float hv = o * fast_tanh(c);
            c_s[tid] = c;
            unsigned word = ((unsigned)(t + 1) << 16)
                          | (unsigned)__half_as_ushort(__float2half_rn(hv));
            st_rlx(&g_htag[t & 1][jmine], word);                     // publish FIRST (critical path)
            hid[(size_t)t * HSZ + jmine] = hv;                       // fp32 for y-GEMM
        }
        // no loop-end barrier: hsh is parity double-buffered; a_s(t+1) writes are
        // ordered after warp0's a_s(t) reads by the staging barrier of step t+1
    }
}

// ---------------- host launcher ----------------
extern "C" void kernel_launch(void* const* d_in, const int* in_sizes, int n_in,
                              void* d_out, int out_size) {
    const float* X  = (const float*)d_in[0];
    const float* Wf = (const float*)d_in[1];
    const float* bf = (const float*)d_in[2];
    const float* Wi = (const float*)d_in[3];
    const float* bi = (const float*)d_in[4];
    const float* Wc = (const float*)d_in[5];
    const float* bc = (const float*)d_in[6];
    const float* Wo = (const float*)d_in[7];
    const float* bo = (const float*)d_in[8];
    const float* Wy = (const float*)d_in[9];
    const float* by = (const float*)d_in[10];

    float* out = (float*)d_out;                       // (T, O) outputs first
    float* hid = out + (size_t)T_SEQ * OSZ;           // then (T, H) hidden states

    cudaFuncSetAttribute(lstm_kernel, cudaFuncAttributeMaxDynamicSharedMemorySize, SMEM_BYTES);

    void* gxp = nullptr;
    cudaGetSymbolAddress(&gxp, g_Gx);
    void* tagp = nullptr;
    cudaGetSymbolAddress(&tagp, g_htag);

    // 0) reset tag buffers (stale tags from a previous graph replay would alias)
    cudaMemsetAsync(tagp, 0, sizeof(unsigned) * 2 * HSZ);

    // 1) fp32 -> fp16 recurrent weights
    conv_w_kernel<<<16384, 256>>>(Wf, Wi, Wc, Wo);

    // 2) Gx[t, g*H+j] = W_g[:, H:] @ x_t + b_g   (M=2048, N=8192, K=1024)
    BDesc bx;
    bx.base[0] = Wf; bx.base[1] = Wi; bx.base[2] = Wc; bx.base[3] = Wo;
    bx.bias[0] = bf; bx.bias[1] = bi; bx.bias[2] = bc; bx.bias[3] = bo;
    bx.ldb = 3072; bx.koff = 2048;
    nt_sgemm128<<<dim3(8192 / 128, T_SEQ / 128), 256>>>(X, ISZ, bx, (float*)gxp, 4 * HSZ, ISZ);

    // 3) persistent recurrence -> writes hidden states
    lstm_kernel<<<NCTA, 256, SMEM_BYTES>>>(hid);

    // 4) y[t] = W_y @ h_t + b_y   (M=2048, N=512, K=2048)
    BDesc byd;
    byd.base[0] = byd.base[1] = byd.base[2] = byd.base[3] = Wy;
    byd.bias[0] = byd.bias[1] = byd.bias[2] = byd.bias[3] = by;
    byd.ldb = HSZ; byd.koff = 0;
    nt_sgemm<<<dim3(OSZ / 64, T_SEQ / 64), 256>>>(hid, HSZ, byd, out, OSZ, HSZ);

    (void)in_sizes; (void)n_in; (void)out_size;
}

// round 17
// speedup vs baseline: 1.4923x; 1.4923x over previous
#include <cuda_runtime.h>
#include <cuda_fp16.h>

// ---------------- problem constants ----------------
#define T_SEQ 2048
#define ISZ   1024
#define HSZ   2048
#define OSZ   512
#define NCTA  148
#define RS    13                 // rows per CTA
#define BASE_ROWS (NCTA*RS)      // 1924
#define EXTRA_ROWS (HSZ - BASE_ROWS) // 124 extra rows (one per CTA < 124)

// SMEM layout (bytes): ws 12 row-gates * 2048 * 2 = 49152 | hsh 4096 | a_s 256 | c_s 64
#define WS_BYTES   49152
#define HSH_OFF    WS_BYTES
#define AS_OFF     (HSH_OFF + 4096)
#define CS_OFF     (AS_OFF + 256)
#define SMEM_BYTES (CS_OFF + 64)

// ---------------- device globals (scratch; no allocation allowed) ----------------
__device__ __half   g_Wh[(size_t)4 * HSZ * HSZ];        // fp16 recurrent weights [g][j][k]
__device__ float    g_Gx[(size_t)T_SEQ * 4 * HSZ];      // [t][g*H + j] = Wx_g @ x_t + b_g
__device__ __align__(16) unsigned g_htag[2][HSZ];       // {tag:16 | h_fp16:16}, dbl-buffered by parity

// ---------------- weight conversion: fp32 -> fp16 (recurrent halves only) ----------------
__global__ void conv_w_kernel(const float* __restrict__ Wf, const float* __restrict__ Wi,
                              const float* __restrict__ Wc, const float* __restrict__ Wo) {
    const float* Ws[4] = {Wf, Wi, Wc, Wo};
    size_t idx = (size_t)blockIdx.x * 256 + threadIdx.x;   // one float4 per thread
    int g   = (int)(idx >> 20);                            // 2048 rows * 512 float4/row
    int rem = (int)(idx & 0xFFFFF);
    int j   = rem >> 9;
    int kv  = rem & 511;
    float4 v = *(const float4*)(Ws[g] + (size_t)j * 3072 + (size_t)kv * 4);
    __half2 h0 = __floats2half2_rn(v.x, v.y);
    __half2 h1 = __floats2half2_rn(v.z, v.w);
    __half2* dst = (__half2*)(g_Wh + ((size_t)(g * HSZ + j)) * HSZ + (size_t)kv * 4);
    dst[0] = h0; dst[1] = h1;
}

// ---------------- NT GEMM descriptors: C[M,N] = A[M,K] * B[N,K]^T + bias(n) ----------------
// B rows indirected: row n lives at base[n>>11] + (n&2047)*ldb + koff.
struct BDesc {
    const float* base[4];
    const float* bias[4];
    int ldb;
    int koff;
};

// 128x128 tile, 8x8 per thread, BK=8, reg-prefetch double buffer. For the big Gx GEMM.
__global__ __launch_bounds__(256) void nt_sgemm128(
    const float* __restrict__ A, int lda,
    BDesc bd,
    float* __restrict__ C, int ldc,
    int K)
{
    __shared__ float As[8][128];
    __shared__ float Bs[8][128];
    int tid = threadIdx.x;
    int m0 = blockIdx.y * 128, n0 = blockIdx.x * 128;
    int lr = tid >> 1;            // 0..127
    int lc = (tid & 1) * 4;       // 0 or 4
    const float* arow = A + (size_t)(m0 + lr) * lda + lc;
    int nb = n0 + lr;
    const float* brow = bd.base[nb >> 11] + (size_t)(nb & 2047) * bd.ldb + bd.koff + lc;
    int tx = (tid & 15) * 8;
    int ty = (tid >> 4) * 8;
    float acc[8][8] = {};

    float4 av = *(const float4*)(arow);
    float4 bv = *(const float4*)(brow);
    for (int k0 = 0; k0 < K; k0 += 8) {
        __syncthreads();
        As[lc + 0][lr] = av.x; As[lc + 1][lr] = av.y;
        As[lc + 2][lr] = av.z; As[lc + 3][lr] = av.w;
        Bs[lc + 0][lr] = bv.x; Bs[lc + 1][lr] = bv.y;
        Bs[lc + 2][lr] = bv.z; Bs[lc + 3][lr] = bv.w;
        __syncthreads();
        if (k0 + 8 < K) {                 // prefetch next slab; overlaps compute below
            av = *(const float4*)(arow + k0 + 8);
            bv = *(const float4*)(brow + k0 + 8);
        }
#pragma unroll
        for (int k = 0; k < 8; k++) {
            float a[8], b[8];
            *(float4*)(a + 0) = *(const float4*)&As[k][ty];
            *(float4*)(a + 4) = *(const float4*)&As[k][ty + 4];
            *(float4*)(b + 0) = *(const float4*)&Bs[k][tx];
            *(float4*)(b + 4) = *(const float4*)&Bs[k][tx + 4];
#pragma unroll
            for (int mi = 0; mi < 8; mi++)
#pragma unroll
                for (int ni = 0; ni < 8; ni++)
                    acc[mi][ni] += a[mi] * b[ni];
        }
    }

    float bias[8];
#pragma unroll
    for (int u = 0; u < 8; u++) {
        int n = n0 + tx + u;
        bias[u] = bd.bias[n >> 11][n & 2047];
    }
#pragma unroll
    for (int mi = 0; mi < 8; mi++) {
        float4 o0, o1;
        o0.x = acc[mi][0] + bias[0]; o0.y = acc[mi][1] + bias[1];
        o0.z = acc[mi][2] + bias[2]; o0.w = acc[mi][3] + bias[3];
        o1.x = acc[mi][4] + bias[4]; o1.y = acc[mi][5] + bias[5];
        o1.z = acc[mi][6] + bias[6]; o1.w = acc[mi][7] + bias[7];
        float* cp = C + (size_t)(m0 + ty + mi) * ldc + n0 + tx;
        *(float4*)cp = o0;
        *(float4*)(cp + 4) = o1;
    }
}

// 64x64 tile, 4x4 per thread. For the small y-GEMM (better grid coverage).
__global__ __launch_bounds__(256) void nt_sgemm(
    const float* __restrict__ A, int lda,
    BDesc bd,
    float* __restrict__ C, int ldc,
    int K)
{
    __shared__ float As[16][64];
    __shared__ float Bs[16][64];
    int tid = threadIdx.x;
    int m0 = blockIdx.y * 64, n0 = blockIdx.x * 64;
    int lrow = tid >> 2;
    int lkv  = (tid & 3) * 4;
    const float* arow = A + (size_t)(m0 + lrow) * lda + lkv;
    int nb = n0 + lrow;
    const float* brow = bd.base[nb >> 11] + (size_t)(nb & 2047) * bd.ldb + bd.koff + lkv;
    int tx = (tid & 15) * 4;
    int ty = (tid >> 4) * 4;
    float acc[4][4] = {};

    for (int k0 = 0; k0 < K; k0 += 16) {
        float4 av = *(const float4*)(arow + k0);
        float4 bv = *(const float4*)(brow + k0);
        __syncthreads();
        As[lkv + 0][lrow] = av.x; As[lkv + 1][lrow] = av.y;
        As[lkv + 2][lrow] = av.z; As[lkv + 3][lrow] = av.w;
        Bs[lkv + 0][lrow] = bv.x; Bs[lkv + 1][lrow] = bv.y;
        Bs[lkv + 2][lrow] = bv.z; Bs[lkv + 3][lrow] = bv.w;
        __syncthreads();
#pragma unroll
        for (int k = 0; k < 16; k++) {
            float4 a4 = *(const float4*)&As[k][ty];
            float4 b4 = *(const float4*)&Bs[k][tx];
            acc[0][0] += a4.x * b4.x; acc[0][1] += a4.x * b4.y; acc[0][2] += a4.x * b4.z; acc[0][3] += a4.x * b4.w;
            acc[1][0] += a4.y * b4.x; acc[1][1] += a4.y * b4.y; acc[1][2] += a4.y * b4.z; acc[1][3] += a4.y * b4.w;
            acc[2][0] += a4.z * b4.x; acc[2][1] += a4.z * b4.y; acc[2][2] += a4.z * b4.z; acc[2][3] += a4.z * b4.w;
            acc[3][0] += a4.w * b4.x; acc[3][1] += a4.w * b4.y; acc[3][2] += a4.w * b4.z; acc[3][3] += a4.w * b4.w;
        }
    }

    float bias[4];
#pragma unroll
    for (int u = 0; u < 4; u++) {
        int n = n0 + tx + u;
        bias[u] = bd.bias[n >> 11][n & 2047];
    }
#pragma unroll
    for (int mi = 0; mi < 4; mi++) {
        float4 o;
        o.x = acc[mi][0] + bias[0];
        o.y = acc[mi][1] + bias[1];
        o.z = acc[mi][2] + bias[2];
        o.w = acc[mi][3] + bias[3];
        *(float4*)(C + (size_t)(m0 + ty + mi) * ldc + n0 + tx) = o;
    }
}

// ---------------- persistent recurrent kernel ----------------
__device__ __forceinline__ float fast_sig(float x)  { return 1.f / (1.f + __expf(-x)); }
__device__ __forceinline__ float fast_tanh(float x) { return 2.f / (1.f + __expf(-2.f * x)) - 1.f; }

__device__ __forceinline__ uint4 ld_vol4(const unsigned* p) {
    uint4 v;
    asm volatile("ld.volatile.global.v4.u32 {%0,%1,%2,%3}, [%4];"
                 : "=r"(v.x), "=r"(v.y), "=r"(v.z), "=r"(v.w) : "l"(p) : "memory");
    return v;
}
__device__ __forceinline__ void st_rlx(unsigned* p, unsigned v) {
    asm volatile("st.relaxed.gpu.global.u32 [%0], %1;" :: "l"(p), "r"(v) : "memory");
}

// one fp16 dot-8 step: p = sum of 8 products in half2, promoted to fp32 (same numerics as R9/R14)
#define MAC8(V, ACC) do {                                            \
    __half2 _p = __hmul2(*(__half2*)&(V).x, h0);                     \
    _p = __hfma2(*(__half2*)&(V).y, h1, _p);                         \
    _p = __hfma2(*(__half2*)&(V).z, h2, _p);                         \
    _p = __hfma2(*(__half2*)&(V).w, h3, _p);                         \
    float2 _pf = __half22float2(_p);                                 \
    (ACC) += _pf.x + _pf.y;                                          \
} while (0)

__global__ __launch_bounds__(256, 1) void lstm_kernel(float* __restrict__ hid) {
    extern __shared__ unsigned char smem[];
    __half* ws  = (__half*)smem;                // 12 row-gates (rg 40..51) * 2048 halfs
    __half* hsh = (__half*)(smem + HSH_OFF);    // 2048 halfs: h_{t-1}
    float*  a_s = (float*)(smem + AS_OFF);      // 56 pre-activations
    float*  c_s = (float*)(smem + CS_OFF);      // 14 cell states

    int cta  = blockIdx.x;
    int tid  = threadIdx.x;
    int w    = tid >> 5;
    int lane = tid & 31;
    bool has_extra = (cta < EXTRA_ROWS);
    int R    = RS + (has_extra ? 1 : 0);
    int row0 = cta * RS;

    // ---- register-resident weights: q = 0..4 (row-gates rg = 8q+w), 160 regs/thread ----
    uint4 wreg[5][8];
    {
        const uint4* base = (const uint4*)g_Wh;
#pragma unroll
        for (int q = 0; q < 5; q++) {
            int rg = 8 * q + w;
            int g = rg & 3, r = rg >> 2;
            const uint4* src = base + ((size_t)(g * HSZ + row0 + r)) * 256 + lane;
#pragma unroll
            for (int i = 0; i < 8; i++) wreg[q][i] = __ldg(src + 32 * i);
        }
    }
    // ---- register-resident extra row (warps 4..7 of CTAs 0..123): 32 regs ----
    uint4 wx[8];
#pragma unroll
    for (int i = 0; i < 8; i++) wx[i] = make_uint4(0, 0, 0, 0);
    if (has_extra && w >= 4) {
        const uint4* src = (const uint4*)g_Wh
                         + ((size_t)((w - 4) * HSZ + BASE_ROWS + cta)) * 256 + lane;
#pragma unroll
        for (int i = 0; i < 8; i++) wx[i] = __ldg(src + 32 * i);
    }

    // ---- SMEM weights: row-gates rg = 40..51 (q=5 all warps; q=6 for w<4) ----
    {
        const uint4* src = (const uint4*)g_Wh;
        uint4* dst = (uint4*)ws;
        for (int ci = tid; ci < 12 * 256; ci += 256) {
            int idx = ci >> 8, off = ci & 255;
            int rg = 40 + idx;
            int g = rg & 3, r = rg >> 2;
            dst[ci] = src[((size_t)(g * HSZ + row0 + r)) * 256 + off];
        }
    }
    if (tid < 16) c_s[tid] = 0.f;
    __syncthreads();

    const uint4* ws5 = (const uint4*)ws + (size_t)w * 256 + lane;        // rg = 40+w
    const uint4* ws6 = (const uint4*)ws + (size_t)(8 + w) * 256 + lane;  // rg = 48+w (w<4)

    for (int t = 0; t < T_SEQ; t++) {
        // ---- prefetch Gx + cell state (independent of h_{t-1}; overlaps the wait) ----
        float gxv0 = 0.f, gxv1 = 0.f, gxv2 = 0.f, gxv3 = 0.f, cold = 0.f;
        int jmine = 0;
        if (tid < R) {
            jmine = (tid < RS) ? (row0 + tid) : (BASE_ROWS + cta);
            const float* gp = g_Gx + (size_t)t * (4 * HSZ) + jmine;
            gxv0 = __ldg(gp);
            gxv1 = __ldg(gp + HSZ);
            gxv2 = __ldg(gp + 2 * HSZ);
            gxv3 = __ldg(gp + 3 * HSZ);
            cold = c_s[tid];
        }

        // ---- acquire h_{t-1}: tagged-word poll, two 128-bit sweeps; spin twice, then sleep ----
        if (t == 0) {
            ((uint4*)hsh)[tid] = make_uint4(0, 0, 0, 0);   // 256*16B = 4KB
        } else {
            const unsigned* src = g_htag[(t - 1) & 1];
            uint4 r0, r1;
            unsigned pend = 3u;
            unsigned tg = (unsigned)t << 16;
            int spins = 0;
            for (;;) {
                if (pend & 1u) {
                    uint4 v = ld_vol4(src + 4 * tid);
                    if ((((v.x ^ tg) | (v.y ^ tg) | (v.z ^ tg) | (v.w ^ tg)) >> 16) == 0u) {
                        r0 = v; pend &= ~1u;
                    }
                }
                if (pend & 2u) {
                    uint4 v = ld_vol4(src + 4 * tid + 1024);
                    if ((((v.x ^ tg) | (v.y ^ tg) | (v.z ^ tg) | (v.w ^ tg)) >> 16) == 0u) {
                        r1 = v; pend &= ~2u;
                    }
                }
                if (!pend) break;
                if (++spins >= 2) __nanosleep(24);   // throttle only if genuinely waiting
            }
            unsigned* hw = (unsigned*)hsh;
            hw[2 * tid + 0]   = (r0.x & 0xFFFFu) | (r0.y << 16);
            hw[2 * tid + 1]   = (r0.z & 0xFFFFu) | (r0.w << 16);
            hw[2 * tid + 512] = (r1.x & 0xFFFFu) | (r1.y << 16);
            hw[2 * tid + 513] = (r1.z & 0xFFFFu) | (r1.w << 16);
        }
        __syncthreads();

        // ---- 56 dot products: q=0..4 + extra from registers, q=5 (+6 for w<4) from SMEM ----
        float acc[7] = {0.f, 0.f, 0.f, 0.f, 0.f, 0.f, 0.f};
        const uint4* h16 = (const uint4*)hsh;
#pragma unroll
        for (int i = 0; i < 8; i++) {
            uint4 hv4 = h16[lane + 32 * i];
            __half2 h0 = *(__half2*)&hv4.x, h1 = *(__half2*)&hv4.y;
            __half2 h2 = *(__half2*)&hv4.z, h3 = *(__half2*)&hv4.w;
            MAC8(wreg[0][i], acc[0]);
            MAC8(wreg[1][i], acc[1]);
            MAC8(wreg[2][i], acc[2]);
            MAC8(wreg[3][i], acc[3]);
            MAC8(wreg[4][i], acc[4]);
            {   // q = 5 from SMEM
                uint4 v = ws5[32 * i];
                MAC8(v, acc[5]);
            }
            if (w < 4) {                           // rg = 48+w from SMEM
                uint4 v = ws6[32 * i];
                MAC8(v, acc[6]);
            } else if (has_extra) {                // extra row from registers
                MAC8(wx[i], acc[6]);
            }
        }

        // ---- joint butterfly reduction of all 7 accumulators (interleaved chains) ----
#pragma unroll
        for (int off = 16; off; off >>= 1) {
#pragma unroll
            for (int q = 0; q < 7; q++)
                acc[q] += __shfl_xor_sync(0xffffffffu, acc[q], off);
        }
        if (lane == 0) {
#pragma unroll
            for (int q = 0; q < 6; q++) a_s[8 * q + w] = acc[q];
            if (w < 4 || has_extra) a_s[48 + w] = acc[6];
        }
        __syncthreads();

        // ---- gate math + state update + publish (one thread per row) ----
        if (tid < R) {
            float af, ai, ac, ao;
            if (tid < RS) {
                af = a_s[tid * 4 + 0]; ai = a_s[tid * 4 + 1];
                ac = a_s[tid * 4 + 2]; ao = a_s[tid * 4 + 3];
            } else {
                af = a_s[52]; ai = a_s[53]; ac = a_s[54]; ao = a_s[55];
            }
            af += gxv0; ai += gxv1; ac += gxv2; ao += gxv3;
            float f  = fast_sig(af);
            float ii = fast_sig(ai);
            float cc = fast_tanh(ac);
            float o  = fast_sig(ao);
            float c  = f * cold + ii * cc;
            float hv = o * fast_tanh(c);
            c_s[tid] = c;
            unsigned word = ((unsigned)(t + 1) << 16)
                          | (unsigned)__half_as_ushort(__float2half_rn(hv));
            st_rlx(&g_htag[t & 1][jmine], word);                     // publish FIRST (critical path)
            hid[(size_t)t * HSZ + jmine] = hv;                       // fp32 for y-GEMM
        }
        __syncthreads();
    }
}

// ---------------- host launcher ----------------
extern "C" void kernel_launch(void* const* d_in, const int* in_sizes, int n_in,
                              void* d_out, int out_size) {
    const float* X  = (const float*)d_in[0];
    const float* Wf = (const float*)d_in[1];
    const float* bf = (const float*)d_in[2];
    const float* Wi = (const float*)d_in[3];
    const float* bi = (const float*)d_in[4];
    const float* Wc = (const float*)d_in[5];
    const float* bc = (const float*)d_in[6];
    const float* Wo = (const float*)d_in[7];
    const float* bo = (const float*)d_in[8];
    const float* Wy = (const float*)d_in[9];
    const float* by = (const float*)d_in[10];

    float* out = (float*)d_out;                       // (T, O) outputs first
    float* hid = out + (size_t)T_SEQ * OSZ;           // then (T, H) hidden states

    cudaFuncSetAttribute(lstm_kernel, cudaFuncAttributeMaxDynamicSharedMemorySize, SMEM_BYTES);

    void* gxp = nullptr;
    cudaGetSymbolAddress(&gxp, g_Gx);
    void* tagp = nullptr;
    cudaGetSymbolAddress(&tagp, g_htag);

    // 0) reset tag buffers (stale tags from a previous graph replay would alias)
    cudaMemsetAsync(tagp, 0, sizeof(unsigned) * 2 * HSZ);

    // 1) fp32 -> fp16 recurrent weights
    conv_w_kernel<<<16384, 256>>>(Wf, Wi, Wc, Wo);

    // 2) Gx[t, g*H+j] = W_g[:, H:] @ x_t + b_g   (M=2048, N=8192, K=1024)
    BDesc bx;
    bx.base[0] = Wf; bx.base[1] = Wi; bx.base[2] = Wc; bx.base[3] = Wo;
    bx.bias[0] = bf; bx.bias[1] = bi; bx.bias[2] = bc; bx.bias[3] = bo;
    bx.ldb = 3072; bx.koff = 2048;
    nt_sgemm128<<<dim3(8192 / 128, T_SEQ / 128), 256>>>(X, ISZ, bx, (float*)gxp, 4 * HSZ, ISZ);

    // 3) persistent recurrence -> writes hidden states
    lstm_kernel<<<NCTA, 256, SMEM_BYTES>>>(hid);

    // 4) y[t] = W_y @ h_t + b_y   (M=2048, N=512, K=2048)
    BDesc byd;
    byd.base[0] = byd.base[1] = byd.base[2] = byd.base[3] = Wy;
    byd.bias[0] = byd.bias[1] = byd.bias[2] = byd.bias[3] = by;
    byd.ldb = HSZ; byd.koff = 0;
    nt_sgemm<<<dim3(OSZ / 64, T_SEQ / 64), 256>>>(hid, HSZ, byd, out, OSZ, HSZ);

    (void)in_sizes; (void)n_in; (void)out_size;
}